// round 2
// baseline (speedup 1.0000x reference)
#include <cuda_runtime.h>

// ---------------- problem constants ----------------
#define BATCH 8
#define CIN   512
#define HF    10
#define WF    25
#define HW    250          // HF*WF
#define CF    64
#define NANCH 2784         // total anchors N
#define MCOL  2783         // N-1
#define DF    640          // CF*HF
#define LDSC  2784         // padded scores row stride
#define KCAT  1280         // 2*DF
#define NINV  (NANCH*HF)   // 27840 mask entries

// ---------------- scratch (device globals; no allocation allowed) ----------------
__device__ __align__(128) float g_xT  [(size_t)BATCH*HW*CIN];        // x transposed [b][hw][c]
__device__ __align__(128) float g_feat[(size_t)BATCH*HW*CF];         // conv out [b][h][w][f]
__device__ __align__(128) float g_pf  [(size_t)BATCH*NANCH*DF];      // pooled features
__device__ __align__(128) float g_sc  [(size_t)BATCH*NANCH*LDSC];    // scores (padded)
__device__ __align__(128) float g_att [(size_t)BATCH*NANCH*DF];      // attention features
__device__ int g_inv_mode;                                           // 0=byte layout, 1=word layout
__device__ unsigned char g_inv[NINV];                                // canonical invalid flags

// ---------------- probe invalid_mask storage layout ----------------
// word layout (int32 0/1 or float32 0.0/1.0): every 4-byte word is 0, 1, or 0x3F800000
// byte layout (bool/int8): some word has a nonzero byte above byte 0 (flags come in runs)
__global__ void k_probe(const unsigned int* __restrict__ w) {
    __shared__ int s_float, s_byte;
    if (threadIdx.x == 0) { s_float = 0; s_byte = 0; }
    __syncthreads();
    // scan first NINV/4 words — in-bounds under both layouts
    for (int i = threadIdx.x; i < NINV/4; i += blockDim.x) {
        unsigned int v = w[i];
        if (v == 0x3F800000u) atomicOr(&s_float, 1);
        else if (v & 0xFFFFFF00u) atomicOr(&s_byte, 1);
    }
    __syncthreads();
    if (threadIdx.x == 0)
        g_inv_mode = (s_float || !s_byte) ? 1 : 0;
}

__global__ void k_expand(const unsigned char* __restrict__ b,
                         const unsigned int* __restrict__ w) {
    int i = blockIdx.x * 256 + threadIdx.x;
    if (i >= NINV) return;
    unsigned char f;
    if (g_inv_mode == 0) f = b[i] ? 1 : 0;       // byte layout
    else                 f = w[i] ? 1 : 0;       // int32 or float32 layout
    g_inv[i] = f;
}

// ---------------- transpose x: (B,512,250) -> (B,250,512) ----------------
__global__ void k_transpose(const float* __restrict__ x) {
    __shared__ float tile[32][33];
    int b  = blockIdx.z;
    int c0 = blockIdx.y * 32;
    int p0 = blockIdx.x * 32;
    for (int i = threadIdx.y; i < 32; i += 8) {
        int c = c0 + i, p = p0 + threadIdx.x;
        float v = 0.f;
        if (c < CIN && p < HW) v = x[((size_t)b*CIN + c)*HW + p];
        tile[i][threadIdx.x] = v;
    }
    __syncthreads();
    for (int i = threadIdx.y; i < 32; i += 8) {
        int p = p0 + i, c = c0 + threadIdx.x;
        if (p < HW && c < CIN)
            g_xT[((size_t)b*HW + p)*CIN + c] = tile[threadIdx.x][i];
    }
}

// ---------------- generic 128x128x16 fp32 GEMM body ----------------
// C[i,n] = sum_k A[i,k] * B(k,n) (+bias[n])
// B_KMAJOR=true : B is (Ncols,K) row-major (NT GEMM)
// B_KMAJOR=false: B is (K,Ncols) row-major (NN GEMM)
template<bool B_KMAJOR>
__device__ __forceinline__ void gemm_body(
    const float* __restrict__ A, const float* __restrict__ B,
    const float* __restrict__ bias, float* __restrict__ C,
    int M, int Ncols, int K, int lda, int ldb, int ldc)
{
    __shared__ float As[16][128];
    __shared__ float Bs[16][128];
    const int tid  = threadIdx.x;
    const int row0 = blockIdx.y * 128;
    const int col0 = blockIdx.x * 128;
    const int ty = tid >> 4, tx = tid & 15;
    const int ry = ty * 8,  cx = tx * 8;

    float acc[8][8];
#pragma unroll
    for (int i = 0; i < 8; i++)
#pragma unroll
        for (int j = 0; j < 8; j++) acc[i][j] = 0.f;

    for (int k0 = 0; k0 < K; k0 += 16) {
#pragma unroll
        for (int l = 0; l < 2; l++) {
            int lin = tid + l*256;
            int r   = lin >> 2;
            int kc  = (lin & 3) * 4;
            float4 v = make_float4(0.f,0.f,0.f,0.f);
            int gr = row0 + r;
            if (gr < M) v = *(const float4*)(A + (size_t)gr*lda + k0 + kc);
            As[kc+0][r]=v.x; As[kc+1][r]=v.y; As[kc+2][r]=v.z; As[kc+3][r]=v.w;
        }
        if (B_KMAJOR) {
#pragma unroll
            for (int l = 0; l < 2; l++) {
                int lin = tid + l*256;
                int r   = lin >> 2;
                int kc  = (lin & 3) * 4;
                float4 v = make_float4(0.f,0.f,0.f,0.f);
                int gc = col0 + r;
                if (gc < Ncols) v = *(const float4*)(B + (size_t)gc*ldb + k0 + kc);
                Bs[kc+0][r]=v.x; Bs[kc+1][r]=v.y; Bs[kc+2][r]=v.z; Bs[kc+3][r]=v.w;
            }
        } else {
#pragma unroll
            for (int l = 0; l < 2; l++) {
                int lin = tid + l*256;
                int r   = lin >> 5;
                int c4  = (lin & 31) * 4;
                float4 v = make_float4(0.f,0.f,0.f,0.f);
                if (col0 + c4 + 3 < Ncols)
                    v = *(const float4*)(B + (size_t)(k0 + r)*ldb + col0 + c4);
                *(float4*)&Bs[r][c4] = v;
            }
        }
        __syncthreads();
#pragma unroll
        for (int k = 0; k < 16; k++) {
            float a[8], bb[8];
            *(float4*)(a)   = *(const float4*)&As[k][ry];
            *(float4*)(a+4) = *(const float4*)&As[k][ry+4];
            *(float4*)(bb)  = *(const float4*)&Bs[k][cx];
            *(float4*)(bb+4)= *(const float4*)&Bs[k][cx+4];
#pragma unroll
            for (int i = 0; i < 8; i++)
#pragma unroll
                for (int j = 0; j < 8; j++) acc[i][j] += a[i]*bb[j];
        }
        __syncthreads();
    }
#pragma unroll
    for (int i = 0; i < 8; i++) {
        int gr = row0 + ry + i;
        if (gr >= M) continue;
#pragma unroll
        for (int j = 0; j < 8; j++) {
            int gc = col0 + cx + j;
            if (gc >= Ncols) continue;
            float v = acc[i][j];
            if (bias) v += bias[gc];
            C[(size_t)gr*ldc + gc] = v;
        }
    }
}

// conv: feat(2000x64) = xT(2000x512) @ conv_w(64x512)^T + conv_b
__global__ __launch_bounds__(256) void k_conv(const float* __restrict__ conv_w,
                                              const float* __restrict__ conv_b) {
    gemm_body<true>(g_xT, conv_w, conv_b, g_feat,
                    BATCH*HW, CF, CIN, CIN, CIN, CF);
}

// gather: pf[b][n][c*HF+h] = invalid[n,h] ? 0 : feat[b][h][xs][c]
__global__ void k_gather(const int* __restrict__ cut_xs) {
    size_t idx = (size_t)blockIdx.x * 256 + threadIdx.x;
    const size_t total = (size_t)BATCH*NANCH*DF;
    if (idx >= total) return;
    int d = (int)(idx % DF);
    size_t r = idx / DF;
    int n = (int)(r % NANCH);
    int b = (int)(r / NANCH);
    int c = d / HF, h = d % HF;
    int xs = cut_xs[n*HF + h];
    float v = 0.f;
    if (!g_inv[n*HF + h])
        v = g_feat[(((size_t)b*HF + h)*WF + xs)*CF + c];
    g_pf[idx] = v;
}

// scores: g_sc[b] (N x MCOL, stride LDSC) = pf[b] @ attn_w^T + attn_b
__global__ __launch_bounds__(256) void k_scores(const float* __restrict__ attn_w,
                                                const float* __restrict__ attn_b) {
    int b = blockIdx.z;
    gemm_body<true>(g_pf + (size_t)b*NANCH*DF, attn_w, attn_b,
                    g_sc + (size_t)b*NANCH*LDSC,
                    NANCH, MCOL, DF, DF, DF, LDSC);
}

// softmax over each row + diagonal scatter into attn output
__global__ __launch_bounds__(256) void k_softmax(float* __restrict__ attn_out) {
    int row = blockIdx.x;
    int i = row % NANCH;
    const float* s = g_sc + (size_t)row * LDSC;
    __shared__ float buf[MCOL];
    __shared__ float red[8];
    int tid = threadIdx.x;

    float mx = -1e30f;
    for (int m = tid; m < MCOL; m += 256) { float v = s[m]; buf[m] = v; mx = fmaxf(mx, v); }
#pragma unroll
    for (int o = 16; o > 0; o >>= 1) mx = fmaxf(mx, __shfl_xor_sync(0xffffffffu, mx, o));
    if ((tid & 31) == 0) red[tid >> 5] = mx;
    __syncthreads();
    float mall = red[0];
#pragma unroll
    for (int w = 1; w < 8; w++) mall = fmaxf(mall, red[w]);

    float sum = 0.f;
    for (int m = tid; m < MCOL; m += 256) { float e = __expf(buf[m] - mall); buf[m] = e; sum += e; }
#pragma unroll
    for (int o = 16; o > 0; o >>= 1) sum += __shfl_xor_sync(0xffffffffu, sum, o);
    __syncthreads();
    if ((tid & 31) == 0) red[tid >> 5] = sum;
    __syncthreads();
    float total = 0.f;
#pragma unroll
    for (int w = 0; w < 8; w++) total += red[w];
    float inv = 1.f / total;

    float* out = attn_out + (size_t)row * NANCH;
    for (int m = tid; m < MCOL; m += 256) {
        int j = m + (m >= i);
        out[j] = buf[m] * inv;
    }
    if (tid == 0) out[i] = 0.f;
}

// att_feats: g_att[b] (N x DF) = attn[b] (N x N) @ pf[b] (N x DF)
__global__ __launch_bounds__(256) void k_attgemm(const float* __restrict__ attn) {
    int b = blockIdx.z;
    gemm_body<false>(attn + (size_t)b*NANCH*NANCH, g_pf + (size_t)b*NANCH*DF,
                     nullptr, g_att + (size_t)b*NANCH*DF,
                     NANCH, DF, NANCH, NANCH, DF, DF);
}

// head: [cls(2)|reg(73)] = cat(att,pf)(22272 x 1280) @ W(75 x 1280)^T + bias,
// fused with lanes assembly for columns 4..76 and cls write.
__global__ __launch_bounds__(256) void k_head(
    const float* __restrict__ cls_w, const float* __restrict__ cls_b,
    const float* __restrict__ reg_w, const float* __restrict__ reg_b,
    const float* __restrict__ anchors,
    float* __restrict__ out_cls, float* __restrict__ out_lanes)
{
    __shared__ float As[16][128];
    __shared__ float Bs[16][128];
    const int tid  = threadIdx.x;
    const int row0 = blockIdx.y * 128;
    const int M = BATCH * NANCH;
    const int ty = tid >> 4, tx = tid & 15;
    const int ry = ty * 8,  cx = tx * 8;

    float acc[8][8];
#pragma unroll
    for (int i = 0; i < 8; i++)
#pragma unroll
        for (int j = 0; j < 8; j++) acc[i][j] = 0.f;

    for (int k0 = 0; k0 < KCAT; k0 += 16) {
        const float* Asrc = (k0 < DF) ? (g_att + k0) : (g_pf + (k0 - DF));
#pragma unroll
        for (int l = 0; l < 2; l++) {
            int lin = tid + l*256;
            int r   = lin >> 2;
            int kc  = (lin & 3) * 4;
            float4 v = make_float4(0.f,0.f,0.f,0.f);
            int gr = row0 + r;
            if (gr < M) v = *(const float4*)(Asrc + (size_t)gr*DF + kc);
            As[kc+0][r]=v.x; As[kc+1][r]=v.y; As[kc+2][r]=v.z; As[kc+3][r]=v.w;
        }
#pragma unroll
        for (int l = 0; l < 2; l++) {
            int lin = tid + l*256;
            int o   = lin >> 2;
            int kc  = (lin & 3) * 4;
            float4 v = make_float4(0.f,0.f,0.f,0.f);
            if (o < 75) {
                const float* wr = (o < 2) ? (cls_w + (size_t)o*KCAT)
                                          : (reg_w + (size_t)(o-2)*KCAT);
                v = *(const float4*)(wr + k0 + kc);
            }
            Bs[kc+0][o]=v.x; Bs[kc+1][o]=v.y; Bs[kc+2][o]=v.z; Bs[kc+3][o]=v.w;
        }
        __syncthreads();
#pragma unroll
        for (int k = 0; k < 16; k++) {
            float a[8], bb[8];
            *(float4*)(a)   = *(const float4*)&As[k][ry];
            *(float4*)(a+4) = *(const float4*)&As[k][ry+4];
            *(float4*)(bb)  = *(const float4*)&Bs[k][cx];
            *(float4*)(bb+4)= *(const float4*)&Bs[k][cx+4];
#pragma unroll
            for (int i = 0; i < 8; i++)
#pragma unroll
                for (int j = 0; j < 8; j++) acc[i][j] += a[i]*bb[j];
        }
        __syncthreads();
    }
#pragma unroll
    for (int i = 0; i < 8; i++) {
        int gr = row0 + ry + i;
        if (gr >= M) continue;
        int n = gr % NANCH;
#pragma unroll
        for (int j = 0; j < 8; j++) {
            int gc = cx + j;
            if (gc >= 75) continue;
            if (gc < 2) {
                out_cls[(size_t)gr*2 + gc] = acc[i][j] + cls_b[gc];
            } else {
                int r = gc - 2;
                float v = acc[i][j] + reg_b[r];
                float base = (r == 0) ? 0.f : anchors[(size_t)n*77 + 4 + r];
                out_lanes[(size_t)gr*77 + 4 + r] = base + v;
            }
        }
    }
}

// lanes columns 0..3 straight from anchors
__global__ void k_lanes_base(const float* __restrict__ anchors,
                             float* __restrict__ out_lanes) {
    int idx = blockIdx.x * 256 + threadIdx.x;
    const int total = BATCH * NANCH * 4;
    if (idx >= total) return;
    int k = idx & 3;
    int r = idx >> 2;
    int n = r % NANCH;
    out_lanes[(size_t)r*77 + k] = anchors[(size_t)n*77 + k];
}

// ---------------- launch ----------------
extern "C" void kernel_launch(void* const* d_in, const int* in_sizes, int n_in,
                              void* d_out, int out_size) {
    // positional defaults (setup_inputs dict order)
    const void* ptr[12];
    for (int i = 0; i < 12 && i < n_in; i++) ptr[i] = d_in[i];
    // size-based binding (robust to metadata reordering); cut_xs precedes invalid_mask
    {
        int seen27840 = 0;
        for (int i = 0; i < n_in; i++) {
            switch (in_sizes[i]) {
                case 1024000: ptr[0]  = d_in[i]; break; // x
                case 32768:   ptr[1]  = d_in[i]; break; // conv_w
                case 64:      ptr[2]  = d_in[i]; break; // conv_b
                case 1781120: ptr[3]  = d_in[i]; break; // attn_w
                case 2783:    ptr[4]  = d_in[i]; break; // attn_b
                case 2560:    ptr[5]  = d_in[i]; break; // cls_w
                case 2:       ptr[6]  = d_in[i]; break; // cls_b
                case 93440:   ptr[7]  = d_in[i]; break; // reg_w
                case 73:      ptr[8]  = d_in[i]; break; // reg_b
                case 214368:  ptr[9]  = d_in[i]; break; // anchors
                case 27840:
                    if (seen27840 == 0) ptr[10] = d_in[i];
                    else                ptr[11] = d_in[i];
                    seen27840++;
                    break;
                default: break;
            }
        }
    }
    const float* x        = (const float*)ptr[0];
    const float* conv_w   = (const float*)ptr[1];
    const float* conv_b   = (const float*)ptr[2];
    const float* attn_w   = (const float*)ptr[3];
    const float* attn_b   = (const float*)ptr[4];
    const float* cls_w    = (const float*)ptr[5];
    const float* cls_b    = (const float*)ptr[6];
    const float* reg_w    = (const float*)ptr[7];
    const float* reg_b    = (const float*)ptr[8];
    const float* anchors  = (const float*)ptr[9];
    const int*   cut_xs   = (const int*)ptr[10];
    const void*  invalid  = ptr[11];

    float* out      = (float*)d_out;
    float* o_cls    = out;
    float* o_lanes  = out + (size_t)BATCH*NANCH*2;
    float* o_attn   = out + (size_t)BATCH*NANCH*79;   // 2 + 77

    k_probe<<<1, 1024>>>((const unsigned int*)invalid);
    k_expand<<<(NINV + 255)/256, 256>>>((const unsigned char*)invalid,
                                        (const unsigned int*)invalid);
    k_transpose<<<dim3(8, 16, BATCH), dim3(32, 8)>>>(x);
    k_conv<<<dim3(1, 16, 1), 256>>>(conv_w, conv_b);
    {
        size_t total = (size_t)BATCH*NANCH*DF;
        k_gather<<<(unsigned)((total + 255)/256), 256>>>(cut_xs);
    }
    k_scores<<<dim3(22, 22, BATCH), 256>>>(attn_w, attn_b);
    k_softmax<<<BATCH*NANCH, 256>>>(o_attn);
    k_attgemm<<<dim3(5, 22, BATCH), 256>>>(o_attn);
    k_head<<<dim3(1, 174, 1), 256>>>(cls_w, cls_b, reg_w, reg_b, anchors,
                                     o_cls, o_lanes);
    k_lanes_base<<<(BATCH*NANCH*4 + 255)/256, 256>>>(anchors, o_lanes);
}

// round 3
// speedup vs baseline: 2.4421x; 2.4421x over previous
#include <cuda_runtime.h>
#include <cstdint>

// ---------------- problem constants ----------------
#define BATCH 8
#define CIN   512
#define HF    10
#define WF    25
#define HW    250          // HF*WF
#define CF    64
#define NANCH 2784         // total anchors N
#define MCOL  2783         // N-1
#define DF    640          // CF*HF
#define LDSC  2784         // padded scores row stride
#define KCAT  1280         // 2*DF
#define NINV  (NANCH*HF)   // 27840 mask entries

// ---------------- scratch (device globals; no allocation allowed) ----------------
__device__ __align__(128) float g_xT  [(size_t)BATCH*HW*CIN];        // x transposed [b][hw][c]
__device__ __align__(128) float g_feat[(size_t)BATCH*HW*CF];         // conv out [b][h][w][f]
__device__ __align__(128) float g_pf  [(size_t)BATCH*NANCH*DF];      // pooled features [b][n][d]
__device__ __align__(128) float g_pfT [(size_t)BATCH*DF*NANCH];      // pf transposed  [b][d][n]
__device__ __align__(128) float g_sc  [(size_t)BATCH*NANCH*LDSC];    // scores (padded)
__device__ __align__(128) float g_att [(size_t)BATCH*NANCH*DF];      // attention features
__device__ int g_inv_mode;
__device__ unsigned char g_inv[NINV];

// ---------------- probe invalid_mask storage layout ----------------
__global__ void k_probe(const unsigned int* __restrict__ w) {
    __shared__ int s_float, s_byte;
    if (threadIdx.x == 0) { s_float = 0; s_byte = 0; }
    __syncthreads();
    for (int i = threadIdx.x; i < NINV/4; i += blockDim.x) {
        unsigned int v = w[i];
        if (v == 0x3F800000u) atomicOr(&s_float, 1);
        else if (v & 0xFFFFFF00u) atomicOr(&s_byte, 1);
    }
    __syncthreads();
    if (threadIdx.x == 0)
        g_inv_mode = (s_float || !s_byte) ? 1 : 0;
}

__global__ void k_expand(const unsigned char* __restrict__ b,
                         const unsigned int* __restrict__ w) {
    int i = blockIdx.x * 256 + threadIdx.x;
    if (i >= NINV) return;
    g_inv[i] = (g_inv_mode == 0) ? (b[i] ? 1 : 0) : (w[i] ? 1 : 0);
}

// ---------------- transpose x: (B,512,250) -> (B,250,512) ----------------
__global__ void k_transpose(const float* __restrict__ x) {
    __shared__ float tile[32][33];
    int b  = blockIdx.z;
    int c0 = blockIdx.y * 32;
    int p0 = blockIdx.x * 32;
    for (int i = threadIdx.y; i < 32; i += 8) {
        int c = c0 + i, p = p0 + threadIdx.x;
        float v = 0.f;
        if (c < CIN && p < HW) v = x[((size_t)b*CIN + c)*HW + p];
        tile[i][threadIdx.x] = v;
    }
    __syncthreads();
    for (int i = threadIdx.y; i < 32; i += 8) {
        int p = p0 + i, c = c0 + threadIdx.x;
        if (p < HW && c < CIN)
            g_xT[((size_t)b*HW + p)*CIN + c] = tile[threadIdx.x][i];
    }
}

// ---------------- pf transpose: [b][n][d] -> [b][d][n] ----------------
__global__ void k_pfT() {
    __shared__ float tile[32][33];
    int b  = blockIdx.z;
    int n0 = blockIdx.x * 32;   // anchor dim (2784 = 32*87)
    int d0 = blockIdx.y * 32;   // feature dim (640 = 32*20)
    const float* src = g_pf + (size_t)b*NANCH*DF;
    float*       dst = g_pfT + (size_t)b*DF*NANCH;
    for (int i = threadIdx.y; i < 32; i += 8)
        tile[i][threadIdx.x] = src[(size_t)(n0 + i)*DF + d0 + threadIdx.x];
    __syncthreads();
    for (int i = threadIdx.y; i < 32; i += 8)
        dst[(size_t)(d0 + i)*NANCH + n0 + threadIdx.x] = tile[threadIdx.x][i];
}

// ================= tf32 tensor-core GEMM =================
// C[m,n] = sum_k A[m,k]*B[n,k] (+bias[n])  — both A and B K-major (NT)
// 128x128 CTA tile, BK=16, 8 warps (2x4), warp tile 64x32, m16n8k8 tf32 mma,
// XOR-swizzled smem, cp.async double buffer.

__device__ __forceinline__ void mma_tf32(float* c, const uint32_t* a, const uint32_t* b) {
    asm volatile(
        "mma.sync.aligned.m16n8k8.row.col.f32.tf32.tf32.f32 "
        "{%0,%1,%2,%3}, {%4,%5,%6,%7}, {%8,%9}, {%0,%1,%2,%3};\n"
        : "+f"(c[0]), "+f"(c[1]), "+f"(c[2]), "+f"(c[3])
        : "r"(a[0]), "r"(a[1]), "r"(a[2]), "r"(a[3]),
          "r"(b[0]), "r"(b[1]));
}

__device__ __forceinline__ int swz(int r, int k) {
    return k ^ (((r >> 1) & 3) << 2);
}

__device__ __forceinline__ void load_tile_async(
    const float* __restrict__ src, int ld, int rmax, int k0,
    float (*dst)[16], int tid)
{
#pragma unroll
    for (int l = 0; l < 2; l++) {
        int lin = tid + l * 256;
        int r   = lin >> 2;
        int kc  = (lin & 3) * 4;
        int cs  = swz(r, kc);
        int rr  = (r < rmax) ? r : 0;
        const float* s = src + (size_t)rr * ld + k0 + kc;
        int sz = (r < rmax) ? 16 : 0;
        unsigned dsts = (unsigned)__cvta_generic_to_shared(&dst[r][cs]);
        asm volatile("cp.async.ca.shared.global [%0], [%1], 16, %2;\n"
                     :: "r"(dsts), "l"(s), "r"(sz));
    }
}

__global__ __launch_bounds__(256, 2) void k_gemm_tf32(
    const float* __restrict__ A, const float* __restrict__ B,
    const float* __restrict__ bias, float* __restrict__ C,
    int M, int N, int K, int lda, int ldb, int ldc,
    size_t sA, size_t sB, size_t sC)
{
    __shared__ float As[2][128][16];
    __shared__ float Bs[2][128][16];
    const int tid = threadIdx.x;
    const int z = blockIdx.z;
    A += sA * z; B += sB * z; C += sC * z;
    const int row0 = blockIdx.y * 128;
    const int col0 = blockIdx.x * 128;
    const int wid = tid >> 5, lane = tid & 31;
    const int warpM = wid >> 2, warpN = wid & 3;
    const int g = lane >> 2, t = lane & 3;

    float acc[4][4][4];
#pragma unroll
    for (int i = 0; i < 4; i++)
#pragma unroll
        for (int j = 0; j < 4; j++)
#pragma unroll
            for (int q = 0; q < 4; q++) acc[i][j][q] = 0.f;

    const float* Ablk = A + (size_t)row0 * lda;
    const float* Bblk = B + (size_t)col0 * ldb;
    int rA = M - row0; if (rA > 128) rA = 128;
    int rB = N - col0; if (rB > 128) rB = 128;

    const int nk = K / 16;
    load_tile_async(Ablk, lda, rA, 0, As[0], tid);
    load_tile_async(Bblk, ldb, rB, 0, Bs[0], tid);
    asm volatile("cp.async.commit_group;\n");

    for (int kb = 0; kb < nk; kb++) {
        if (kb + 1 < nk) {
            load_tile_async(Ablk, lda, rA, (kb + 1) * 16, As[(kb + 1) & 1], tid);
            load_tile_async(Bblk, ldb, rB, (kb + 1) * 16, Bs[(kb + 1) & 1], tid);
            asm volatile("cp.async.commit_group;\n");
            asm volatile("cp.async.wait_group 1;\n");
        } else {
            asm volatile("cp.async.wait_group 0;\n");
        }
        __syncthreads();
        const int st = kb & 1;
#pragma unroll
        for (int ks = 0; ks < 2; ks++) {
            const int kk = ks * 8;
            uint32_t a[4][4], b[4][2];
#pragma unroll
            for (int i = 0; i < 4; i++) {
                int m  = warpM * 64 + i * 16 + g;
                a[i][0] = __float_as_uint(As[st][m    ][swz(m,     kk + t    )]);
                a[i][1] = __float_as_uint(As[st][m + 8][swz(m + 8, kk + t    )]);
                a[i][2] = __float_as_uint(As[st][m    ][swz(m,     kk + t + 4)]);
                a[i][3] = __float_as_uint(As[st][m + 8][swz(m + 8, kk + t + 4)]);
            }
#pragma unroll
            for (int j = 0; j < 4; j++) {
                int n = warpN * 32 + j * 8 + g;
                b[j][0] = __float_as_uint(Bs[st][n][swz(n, kk + t    )]);
                b[j][1] = __float_as_uint(Bs[st][n][swz(n, kk + t + 4)]);
            }
#pragma unroll
            for (int i = 0; i < 4; i++)
#pragma unroll
                for (int j = 0; j < 4; j++)
                    mma_tf32(acc[i][j], a[i], b[j]);
        }
        __syncthreads();
    }

    // epilogue
#pragma unroll
    for (int i = 0; i < 4; i++) {
        int gm0 = row0 + warpM * 64 + i * 16 + g;
#pragma unroll
        for (int j = 0; j < 4; j++) {
            int gn = col0 + warpN * 32 + j * 8 + 2 * t;
            float b0 = 0.f, b1 = 0.f;
            if (bias) {
                if (gn     < N) b0 = bias[gn];
                if (gn + 1 < N) b1 = bias[gn + 1];
            }
#pragma unroll
            for (int h = 0; h < 2; h++) {
                int gm = gm0 + h * 8;
                if (gm >= M) continue;
                float c0 = acc[i][j][2*h]     + b0;
                float c1 = acc[i][j][2*h + 1] + b1;
                float* dst = C + (size_t)gm * ldc + gn;
                if (gn + 1 < N)      *(float2*)dst = make_float2(c0, c1);
                else if (gn < N)     *dst = c0;
            }
        }
    }
}

// gather: pf[b][n][c*HF+h] = invalid[n,h] ? 0 : feat[b][h][xs][c]
__global__ void k_gather(const int* __restrict__ cut_xs) {
    size_t idx = (size_t)blockIdx.x * 256 + threadIdx.x;
    const size_t total = (size_t)BATCH*NANCH*DF;
    if (idx >= total) return;
    int d = (int)(idx % DF);
    size_t r = idx / DF;
    int n = (int)(r % NANCH);
    int b = (int)(r / NANCH);
    int c = d / HF, h = d % HF;
    int xs = cut_xs[n*HF + h];
    float v = 0.f;
    if (!g_inv[n*HF + h])
        v = g_feat[(((size_t)b*HF + h)*WF + xs)*CF + c];
    g_pf[idx] = v;
}

// softmax over each row + diagonal scatter into attn output
__global__ __launch_bounds__(256) void k_softmax(float* __restrict__ attn_out) {
    int row = blockIdx.x;
    int i = row % NANCH;
    const float* s = g_sc + (size_t)row * LDSC;
    __shared__ float buf[MCOL];
    __shared__ float red[8];
    int tid = threadIdx.x;

    float mx = -1e30f;
    for (int m = tid; m < MCOL; m += 256) { float v = s[m]; buf[m] = v; mx = fmaxf(mx, v); }
#pragma unroll
    for (int o = 16; o > 0; o >>= 1) mx = fmaxf(mx, __shfl_xor_sync(0xffffffffu, mx, o));
    if ((tid & 31) == 0) red[tid >> 5] = mx;
    __syncthreads();
    float mall = red[0];
#pragma unroll
    for (int w = 1; w < 8; w++) mall = fmaxf(mall, red[w]);

    float sum = 0.f;
    for (int m = tid; m < MCOL; m += 256) { float e = __expf(buf[m] - mall); buf[m] = e; sum += e; }
#pragma unroll
    for (int o = 16; o > 0; o >>= 1) sum += __shfl_xor_sync(0xffffffffu, sum, o);
    __syncthreads();
    if ((tid & 31) == 0) red[tid >> 5] = sum;
    __syncthreads();
    float total = 0.f;
#pragma unroll
    for (int w = 0; w < 8; w++) total += red[w];
    float inv = 1.f / total;

    float* out = attn_out + (size_t)row * NANCH;
    for (int m = tid; m < MCOL; m += 256) {
        int j = m + (m >= i);
        out[j] = buf[m] * inv;
    }
    if (tid == 0) out[i] = 0.f;
}

// head: [cls(2)|reg(73)] = cat(att,pf)(22272 x 1280) @ W(75 x 1280)^T + bias
__global__ __launch_bounds__(256) void k_head(
    const float* __restrict__ cls_w, const float* __restrict__ cls_b,
    const float* __restrict__ reg_w, const float* __restrict__ reg_b,
    const float* __restrict__ anchors,
    float* __restrict__ out_cls, float* __restrict__ out_lanes)
{
    __shared__ float As[16][128];
    __shared__ float Bs[16][128];
    const int tid  = threadIdx.x;
    const int row0 = blockIdx.y * 128;
    const int M = BATCH * NANCH;
    const int ty = tid >> 4, tx = tid & 15;
    const int ry = ty * 8,  cx = tx * 8;

    float acc[8][8];
#pragma unroll
    for (int i = 0; i < 8; i++)
#pragma unroll
        for (int j = 0; j < 8; j++) acc[i][j] = 0.f;

    for (int k0 = 0; k0 < KCAT; k0 += 16) {
        const float* Asrc = (k0 < DF) ? (g_att + k0) : (g_pf + (k0 - DF));
#pragma unroll
        for (int l = 0; l < 2; l++) {
            int lin = tid + l*256;
            int r   = lin >> 2;
            int kc  = (lin & 3) * 4;
            float4 v = make_float4(0.f,0.f,0.f,0.f);
            int gr = row0 + r;
            if (gr < M) v = *(const float4*)(Asrc + (size_t)gr*DF + kc);
            As[kc+0][r]=v.x; As[kc+1][r]=v.y; As[kc+2][r]=v.z; As[kc+3][r]=v.w;
        }
#pragma unroll
        for (int l = 0; l < 2; l++) {
            int lin = tid + l*256;
            int o   = lin >> 2;
            int kc  = (lin & 3) * 4;
            float4 v = make_float4(0.f,0.f,0.f,0.f);
            if (o < 75) {
                const float* wr = (o < 2) ? (cls_w + (size_t)o*KCAT)
                                          : (reg_w + (size_t)(o-2)*KCAT);
                v = *(const float4*)(wr + k0 + kc);
            }
            Bs[kc+0][o]=v.x; Bs[kc+1][o]=v.y; Bs[kc+2][o]=v.z; Bs[kc+3][o]=v.w;
        }
        __syncthreads();
#pragma unroll
        for (int k = 0; k < 16; k++) {
            float a[8], bb[8];
            *(float4*)(a)   = *(const float4*)&As[k][ry];
            *(float4*)(a+4) = *(const float4*)&As[k][ry+4];
            *(float4*)(bb)  = *(const float4*)&Bs[k][cx];
            *(float4*)(bb+4)= *(const float4*)&Bs[k][cx+4];
#pragma unroll
            for (int i = 0; i < 8; i++)
#pragma unroll
                for (int j = 0; j < 8; j++) acc[i][j] += a[i]*bb[j];
        }
        __syncthreads();
    }
#pragma unroll
    for (int i = 0; i < 8; i++) {
        int gr = row0 + ry + i;
        if (gr >= M) continue;
        int n = gr % NANCH;
#pragma unroll
        for (int j = 0; j < 8; j++) {
            int gc = cx + j;
            if (gc >= 75) continue;
            if (gc < 2) {
                out_cls[(size_t)gr*2 + gc] = acc[i][j] + cls_b[gc];
            } else {
                int r = gc - 2;
                float v = acc[i][j] + reg_b[r];
                float base = (r == 0) ? 0.f : anchors[(size_t)n*77 + 4 + r];
                out_lanes[(size_t)gr*77 + 4 + r] = base + v;
            }
        }
    }
}

// lanes columns 0..3 straight from anchors
__global__ void k_lanes_base(const float* __restrict__ anchors,
                             float* __restrict__ out_lanes) {
    int idx = blockIdx.x * 256 + threadIdx.x;
    const int total = BATCH * NANCH * 4;
    if (idx >= total) return;
    int k = idx & 3;
    int r = idx >> 2;
    int n = r % NANCH;
    out_lanes[(size_t)r*77 + k] = anchors[(size_t)n*77 + k];
}

// ---------------- launch ----------------
extern "C" void kernel_launch(void* const* d_in, const int* in_sizes, int n_in,
                              void* d_out, int out_size) {
    const void* ptr[12];
    for (int i = 0; i < 12 && i < n_in; i++) ptr[i] = d_in[i];
    {
        int seen27840 = 0;
        for (int i = 0; i < n_in; i++) {
            switch (in_sizes[i]) {
                case 1024000: ptr[0]  = d_in[i]; break; // x
                case 32768:   ptr[1]  = d_in[i]; break; // conv_w
                case 64:      ptr[2]  = d_in[i]; break; // conv_b
                case 1781120: ptr[3]  = d_in[i]; break; // attn_w
                case 2783:    ptr[4]  = d_in[i]; break; // attn_b
                case 2560:    ptr[5]  = d_in[i]; break; // cls_w
                case 2:       ptr[6]  = d_in[i]; break; // cls_b
                case 93440:   ptr[7]  = d_in[i]; break; // reg_w
                case 73:      ptr[8]  = d_in[i]; break; // reg_b
                case 214368:  ptr[9]  = d_in[i]; break; // anchors
                case 27840:
                    if (seen27840 == 0) ptr[10] = d_in[i];
                    else                ptr[11] = d_in[i];
                    seen27840++;
                    break;
                default: break;
            }
        }
    }
    const float* x        = (const float*)ptr[0];
    const float* conv_w   = (const float*)ptr[1];
    const float* conv_b   = (const float*)ptr[2];
    const float* attn_w   = (const float*)ptr[3];
    const float* attn_b   = (const float*)ptr[4];
    const float* cls_w    = (const float*)ptr[5];
    const float* cls_b    = (const float*)ptr[6];
    const float* reg_w    = (const float*)ptr[7];
    const float* reg_b    = (const float*)ptr[8];
    const float* anchors  = (const float*)ptr[9];
    const int*   cut_xs   = (const int*)ptr[10];
    const void*  invalid  = ptr[11];

    float* out      = (float*)d_out;
    float* o_cls    = out;
    float* o_lanes  = out + (size_t)BATCH*NANCH*2;
    float* o_attn   = out + (size_t)BATCH*NANCH*79;   // 2 + 77

    float* pf   = nullptr; cudaGetSymbolAddress((void**)&pf,   g_pf);
    float* pfT  = nullptr; cudaGetSymbolAddress((void**)&pfT,  g_pfT);
    float* sc   = nullptr; cudaGetSymbolAddress((void**)&sc,   g_sc);
    float* att  = nullptr; cudaGetSymbolAddress((void**)&att,  g_att);
    float* xT   = nullptr; cudaGetSymbolAddress((void**)&xT,   g_xT);
    float* feat = nullptr; cudaGetSymbolAddress((void**)&feat, g_feat);

    k_probe<<<1, 1024>>>((const unsigned int*)invalid);
    k_expand<<<(NINV + 255)/256, 256>>>((const unsigned char*)invalid,
                                        (const unsigned int*)invalid);
    k_transpose<<<dim3(8, 16, BATCH), dim3(32, 8)>>>(x);

    // conv: feat(2000x64) = xT(2000x512) @ conv_w(64x512)^T + conv_b   [tf32 NT]
    k_gemm_tf32<<<dim3(1, 16, 1), 256>>>(xT, conv_w, conv_b, feat,
                                         BATCH*HW, CF, CIN, CIN, CIN, CF,
                                         0, 0, 0);
    {
        size_t total = (size_t)BATCH*NANCH*DF;
        k_gather<<<(unsigned)((total + 255)/256), 256>>>(cut_xs);
    }
    k_pfT<<<dim3(NANCH/32, DF/32, BATCH), dim3(32, 8)>>>();

    // scores[b] (2784 x 2783) = pf[b] @ attn_w^T + attn_b   [tf32 NT]
    k_gemm_tf32<<<dim3(22, 22, BATCH), 256>>>(pf, attn_w, attn_b, sc,
                                              NANCH, MCOL, DF, DF, DF, LDSC,
                                              (size_t)NANCH*DF, 0, (size_t)NANCH*LDSC);
    k_softmax<<<BATCH*NANCH, 256>>>(o_attn);

    // att[b] (2784 x 640) = attn[b] @ pf[b] = attn[b] @ pfT[b]^T   [tf32 NT]
    k_gemm_tf32<<<dim3(5, 22, BATCH), 256>>>(o_attn, pfT, nullptr, att,
                                             NANCH, DF, NANCH, NANCH, NANCH, DF,
                                             (size_t)NANCH*NANCH, (size_t)DF*NANCH,
                                             (size_t)NANCH*DF);
    k_head<<<dim3(1, 174, 1), 256>>>(cls_w, cls_b, reg_w, reg_b, anchors,
                                     o_cls, o_lanes);
    k_lanes_base<<<(BATCH*NANCH*4 + 255)/256, 256>>>(anchors, o_lanes);
}